// round 4
// baseline (speedup 1.0000x reference)
#include <cuda_runtime.h>
#include <cstdint>

// Fixed problem shapes: E=4096, IN=OUT=256, N_NODES=1024
#define MAX_E 4096
#define NN    1024
#define FC    256          // feature channels
#define FC4   64           // float4 chunks per row

// ---------------- device scratch ----------------
__device__ int   g_flagA;            // nonzero byte at misaligned index -> byte layout
__device__ int   g_flagNZ;           // any nonzero byte
__device__ int   g_hs[NN], g_hd[NN], g_sl[NN];
__device__ int   g_off_src[NN + 1], g_off_dst[NN + 1];
__device__ int   g_cur_src[NN], g_cur_dst[NN];
__device__ int   g_lst_src[MAX_E], g_lst_dst[MAX_E];
__device__ float g_w[MAX_E];         // s_e / sqrt(deg_e)  (0 for self-loops)
__device__ float g_t[NN * FC];       // t = B (w .* x)      (overwritten, no zero needed)
__device__ float g_T[NN * FC];       // T = t @ W^T

// ============ K0: zero small scratch (1 block) =============================
__global__ __launch_bounds__(1024)
void k_zero() {
    int i = threadIdx.x;
    g_hs[i] = 0; g_hd[i] = 0; g_sl[i] = 0;
    if (i == 0) { g_flagA = 0; g_flagNZ = 0; }
}

// ============ K1: per-edge histograms + bool-layout detection ==============
__global__ void k_hist(const int* __restrict__ ei,
                       const unsigned char* __restrict__ b, int E) {
    int e = blockIdx.x * blockDim.x + threadIdx.x;
    if (e >= E) return;
    unsigned char v = b[e];
    if (v) {
        atomicOr(&g_flagNZ, 1);
        if (e & 3) atomicOr(&g_flagA, 1);
    }
    int s = ei[e], d = ei[E + e];
    atomicAdd(&g_hs[s], 1);
    atomicAdd(&g_hd[d], 1);
    if (s == d) atomicAdd(&g_sl[s], 1);
}

// ============ K2: exclusive scan of both histograms (warp-shuffle) =========
__global__ __launch_bounds__(1024)
void k_scan() {
    int t = threadIdx.x;
    int lane = t & 31, wid = t >> 5;
    int vs = g_hs[t], vd = g_hd[t];
    #pragma unroll
    for (int o = 1; o < 32; o <<= 1) {
        int a = __shfl_up_sync(0xffffffffu, vs, o); if (lane >= o) vs += a;
        int b = __shfl_up_sync(0xffffffffu, vd, o); if (lane >= o) vd += b;
    }
    __shared__ int ws[32], wd[32];
    if (lane == 31) { ws[wid] = vs; wd[wid] = vd; }
    __syncthreads();
    if (wid == 0) {
        int a = ws[lane], b = wd[lane];
        #pragma unroll
        for (int o = 1; o < 32; o <<= 1) {
            int xa = __shfl_up_sync(0xffffffffu, a, o); if (lane >= o) a += xa;
            int xb = __shfl_up_sync(0xffffffffu, b, o); if (lane >= o) b += xb;
        }
        ws[lane] = a; wd[lane] = b;
    }
    __syncthreads();
    int offs = wid ? ws[wid - 1] : 0;
    int offd = wid ? wd[wid - 1] : 0;
    g_off_src[t + 1] = vs + offs;
    g_off_dst[t + 1] = vd + offd;
    if (t == 0) { g_off_src[0] = 0; g_off_dst[0] = 0; }
    g_cur_src[t] = 0; g_cur_dst[t] = 0;
}

// ============ K3: weights + CSR fill =======================================
__global__ void k_fillw(const int* __restrict__ ei, const void* __restrict__ isdir,
                        int E) {
    int e = blockIdx.x * blockDim.x + threadIdx.x;
    if (e >= E) return;
    int s = ei[e], d = ei[E + e];
    float w = 0.0f;
    if (s != d) {
        int deg = g_hs[s] + g_hd[s] + g_hs[d] + g_hd[d]
                - 2 * (g_sl[s] + g_sl[d]);             // integer-exact
        int dir;
        if (g_flagA)       dir = ((const unsigned char*)isdir)[e] != 0;
        else if (g_flagNZ) dir = ((const int*)isdir)[e] != 0;
        else               dir = 0;
        w = (dir ? -1.0f : 1.0f) * rsqrtf((float)deg);
    }
    g_w[e] = w;
    int p = g_off_src[s] + atomicAdd(&g_cur_src[s], 1);
    g_lst_src[p] = e;
    int q = g_off_dst[d] + atomicAdd(&g_cur_dst[d], 1);
    g_lst_dst[q] = e;
}

// ============ K4: gather t[n] = sum_dst w*x - sum_src w*x ==================
// block per node, 64 threads = 64 float4 channel chunks
#define CAP 64
__global__ __launch_bounds__(64)
void k_tg(const float* __restrict__ x) {
    int n = blockIdx.x;
    int t = threadIdx.x;
    __shared__ float sw[CAP];
    __shared__ int   se[CAP];
    float4 acc = make_float4(0.f, 0.f, 0.f, 0.f);

    #pragma unroll
    for (int side = 0; side < 2; side++) {
        int lo, hi; const int* lst; float sgn;
        if (side == 0) { lo = g_off_src[n]; hi = g_off_src[n + 1]; lst = g_lst_src; sgn = -1.f; }
        else           { lo = g_off_dst[n]; hi = g_off_dst[n + 1]; lst = g_lst_dst; sgn =  1.f; }
        for (int base = lo; base < hi; base += CAP) {
            int m = min(CAP, hi - base);
            if (t < m) {
                int e = lst[base + t];
                se[t] = e;
                sw[t] = sgn * g_w[e];
            }
            __syncthreads();
            for (int j = 0; j < m; j++) {
                float w = sw[j];
                float4 v = ((const float4*)x)[se[j] * FC4 + t];
                acc.x = fmaf(w, v.x, acc.x);
                acc.y = fmaf(w, v.y, acc.y);
                acc.z = fmaf(w, v.z, acc.z);
                acc.w = fmaf(w, v.w, acc.w);
            }
            __syncthreads();
        }
    }
    ((float4*)g_t)[n * FC4 + t] = acc;
}

// ============ K5: GEMM  T[m][n] = sum_k t[m][k] * W[n][k] ==================
#define BM 32
#define BN 64
#define BK 16
__global__ __launch_bounds__(128)
void k_gemm(const float* __restrict__ B /* W [N,K] */) {
    __shared__ float As[BK][BM + 1];
    __shared__ float Bs[BK][BN + 1];
    int gx = blockIdx.x & 3;
    int gy = blockIdx.x >> 2;
    int m0 = gy * BM;
    int n0 = gx * BN;
    int tid = threadIdx.x;
    int tx = tid & 15;
    int ty = tid >> 4;

    float acc[4][4];
    #pragma unroll
    for (int i = 0; i < 4; i++)
        #pragma unroll
        for (int j = 0; j < 4; j++) acc[i][j] = 0.0f;

    for (int k0 = 0; k0 < FC; k0 += BK) {
        {
            int row = tid >> 2;
            int kq  = (tid & 3) << 2;
            float4 v = *(const float4*)&g_t[(m0 + row) * FC + k0 + kq];
            As[kq + 0][row] = v.x; As[kq + 1][row] = v.y;
            As[kq + 2][row] = v.z; As[kq + 3][row] = v.w;
        }
        #pragma unroll
        for (int r = 0; r < 2; r++) {
            int idx = tid + 128 * r;
            int n   = idx >> 2;
            int kq  = (idx & 3) << 2;
            float4 v = *(const float4*)&B[(n0 + n) * FC + k0 + kq];
            Bs[kq + 0][n] = v.x; Bs[kq + 1][n] = v.y;
            Bs[kq + 2][n] = v.z; Bs[kq + 3][n] = v.w;
        }
        __syncthreads();

        #pragma unroll
        for (int k = 0; k < BK; k++) {
            float a[4], bb[4];
            #pragma unroll
            for (int i = 0; i < 4; i++) a[i]  = As[k][ty * 4 + i];
            #pragma unroll
            for (int j = 0; j < 4; j++) bb[j] = Bs[k][tx * 4 + j];
            #pragma unroll
            for (int i = 0; i < 4; i++)
                #pragma unroll
                for (int j = 0; j < 4; j++)
                    acc[i][j] = fmaf(a[i], bb[j], acc[i][j]);
        }
        __syncthreads();
    }

    #pragma unroll
    for (int i = 0; i < 4; i++) {
        float4 v = make_float4(acc[i][0], acc[i][1], acc[i][2], acc[i][3]);
        *(float4*)&g_T[(m0 + ty * 4 + i) * FC + n0 + tx * 4] = v;
    }
}

// ============ K6: final  y_e = w_e * (T[dst_e] - T[src_e]) =================
__global__ __launch_bounds__(256)
void k_gather(const int* __restrict__ ei, float* __restrict__ y, int E) {
    int t = blockIdx.x * blockDim.x + threadIdx.x;
    int e  = t >> 6;
    int c4 = t & 63;
    if (e >= E) return;
    float w = g_w[e];
    int s = ei[e], d = ei[E + e];
    float4 vd = ((const float4*)g_T)[d * FC4 + c4];
    float4 vs = ((const float4*)g_T)[s * FC4 + c4];
    float4 o;
    o.x = w * (vd.x - vs.x); o.y = w * (vd.y - vs.y);
    o.z = w * (vd.z - vs.z); o.w = w * (vd.w - vs.w);
    ((float4*)y)[e * FC4 + c4] = o;
}

// ---------------- launch ---------------------------------------------------
extern "C" void kernel_launch(void* const* d_in, const int* in_sizes, int n_in,
                              void* d_out, int out_size) {
    const float* x     = (const float*)d_in[0];   // [E, 256]
    const float* W     = (const float*)d_in[1];   // [256, 256]
    const int*   ei    = (const int*)d_in[2];     // [2, E]
    const void*  isdir = d_in[3];                 // [E] bool or int32

    int E = in_sizes[2] / 2;
    float* y = (float*)d_out;

    k_zero<<<1, 1024>>>();
    k_hist<<<(E + 255) / 256, 256>>>(ei, (const unsigned char*)isdir, E);
    k_scan<<<1, 1024>>>();
    k_fillw<<<(E + 255) / 256, 256>>>(ei, isdir, E);
    k_tg<<<NN, 64>>>(x);
    k_gemm<<<128, 128>>>(W);
    k_gather<<<(E * FC4 + 255) / 256, 256>>>(ei, y, E);
}